// round 12
// baseline (speedup 1.0000x reference)
#include <cuda_runtime.h>
#include <cuda_fp16.h>
#include <math.h>
#include <stdint.h>

// ===========================================================================
// MySupConLoss fused, round 10: symmetric mma.sync GEMM + in-loop mask
// streaming. Masks cp.async'd into SMEM (16 KB/kt) inside the k-loop and
// ballot-compressed to an 8 KB bit array -> epilogues do ZERO global mask
// traffic (kills the 4x sector amplification of transposed scalar reads)
// and the 512 MB mask stream overlaps the HMMA phase.
// ===========================================================================

#define NROWS 8192
#define DDIM  512
#define INV_T 14.285714285714286f
#define EXP_C2 20.60992915555662f   // INV_T * log2(e)

#define BM 128
#define BN 128
#define BK 32
#define NKT (DDIM / BK)        // 16
#define PITCH_B 80             // bytes per smem row (32 halves + 8 pad)
#define TILE_BYTES (128 * PITCH_B)      // 10240
#define STAGE_BYTES (2 * TILE_BYTES)    // 20480 (A + B)
#define NST 3
#define GEMM_SMEM (NST * STAGE_BYTES)   // 61440
#define MSTAGE_BYTES 16384              // one mask chunk (4096 ints)
#define OFF_MSTAGE GEMM_SMEM            // 2 slots
#define OFF_BITS  (GEMM_SMEM + 2 * MSTAGE_BYTES)   // 94208
#define SMEM_MAIN (OFF_BITS + 2048 * 4)            // 102400
#define THREADS 256
#define NBLK (NROWS / BM)
#define NPAIR (NBLK * (NBLK + 1) / 2)   // 2080

// bit array layout (2048 words): [0,512) posRow, [512,1024) negRow,
// [1024,1536) posCol, [1536,2048) negCol; linear word index = kt*128 + g'.

// ---------------------------------------------------------------------------
__device__ __half g_fn16[(size_t)NROWS * DDIM];
__device__ float  g_einv[NROWS];   // exp(-m_i)
__device__ float  g_spos[NROWS];
__device__ float  g_sneg[NROWS];
__device__ float  g_card[NROWS];

// ---------------------------------------------------------------------------
__device__ __forceinline__ uint32_t smem_u32(const void* p) {
    uint32_t a;
    asm("{ .reg .u64 t; cvta.to.shared.u64 t, %1; cvt.u32.u64 %0, t; }"
        : "=r"(a) : "l"(p));
    return a;
}
__device__ __forceinline__ void cp16(uint32_t s, const void* g) {
    asm volatile("cp.async.cg.shared.global [%0], [%1], 16;"
                 :: "r"(s), "l"(g) : "memory");
}
__device__ __forceinline__ void cp_commit() {
    asm volatile("cp.async.commit_group;" ::: "memory");
}
__device__ __forceinline__ void cp_wait1() {
    asm volatile("cp.async.wait_group 1;" ::: "memory");
}
__device__ __forceinline__ void ldm_x4(uint32_t a, uint32_t& r0, uint32_t& r1,
                                       uint32_t& r2, uint32_t& r3) {
    asm volatile("ldmatrix.sync.aligned.m8n8.x4.shared.b16 {%0,%1,%2,%3}, [%4];"
                 : "=r"(r0), "=r"(r1), "=r"(r2), "=r"(r3) : "r"(a));
}
__device__ __forceinline__ void mma16816(float* c, const uint32_t* a,
                                         uint32_t b0, uint32_t b1) {
    asm volatile(
        "mma.sync.aligned.m16n8k16.row.col.f32.f16.f16.f32 "
        "{%0,%1,%2,%3}, {%4,%5,%6,%7}, {%8,%9}, {%0,%1,%2,%3};"
        : "+f"(c[0]), "+f"(c[1]), "+f"(c[2]), "+f"(c[3])
        : "r"(a[0]), "r"(a[1]), "r"(a[2]), "r"(a[3]), "r"(b0), "r"(b1));
}

// ---------------------------------------------------------------------------
// Kernel 1: normalize -> fp16, einv = exp(-m_i), zero accumulators + out
// ---------------------------------------------------------------------------
__global__ __launch_bounds__(128) void k_normalize(const float* __restrict__ f,
                                                   float* __restrict__ out) {
    int row = blockIdx.x;
    const float4* fr = reinterpret_cast<const float4*>(f + (size_t)row * DDIM);
    float4 v = fr[threadIdx.x];
    float ss = v.x * v.x + v.y * v.y + v.z * v.z + v.w * v.w;
    #pragma unroll
    for (int o = 16; o; o >>= 1) ss += __shfl_xor_sync(0xffffffffu, ss, o);
    __shared__ float s[4];
    if ((threadIdx.x & 31) == 0) s[threadIdx.x >> 5] = ss;
    __syncthreads();
    float tot = s[0] + s[1] + s[2] + s[3];
    float inv = 1.0f / fmaxf(sqrtf(tot), 1e-8f);
    __half2 h0 = __floats2half2_rn(v.x * inv, v.y * inv);
    __half2 h1 = __floats2half2_rn(v.z * inv, v.w * inv);
    __half2* o2 = reinterpret_cast<__half2*>(g_fn16 + (size_t)row * DDIM);
    o2[threadIdx.x * 2 + 0] = h0;
    o2[threadIdx.x * 2 + 1] = h1;
    if (threadIdx.x == 0) {
        g_einv[row] = expf(-(tot * inv * inv * INV_T));
        g_spos[row] = 0.f; g_sneg[row] = 0.f; g_card[row] = 0.f;
        if (row == 0) out[0] = 0.f;
    }
}

// ---------------------------------------------------------------------------
// Kernel 2: fused symmetric GEMM + mask streaming + dual epilogue.
// ---------------------------------------------------------------------------
__global__ __launch_bounds__(THREADS, 2) void k_main(const int* __restrict__ pos,
                                                     const int* __restrict__ neg) {
    extern __shared__ __align__(16) char smem_raw[];
    const uint32_t sbase = smem_u32(smem_raw);
    uint32_t* const smBits = reinterpret_cast<uint32_t*>(smem_raw + OFF_BITS);
    const int* const smStage = reinterpret_cast<const int*>(smem_raw + OFF_MSTAGE);

    // linear block id -> upper-triangular (bi <= bj)
    int idx = blockIdx.x, bi = 0, len = NBLK;
    while (idx >= len) { idx -= len; bi++; len--; }
    const int bj = bi + idx;
    const bool offdiag = (bi != bj);

    const int tid = threadIdx.x;
    const int wid = tid >> 5;
    const int lane = tid & 31;
    const int warpM = wid & 3;
    const int warpN = wid >> 2;
    const int rowBase = bi * BM;
    const int colBase = bj * BN;

    const int lr = tid >> 2;
    const int ck = tid & 3;
    const __half* gA = g_fn16 + (size_t)(rowBase + lr) * DDIM + ck * 8;
    const __half* gB = g_fn16 + (size_t)(colBase + lr) * DDIM + ck * 8;
    const uint32_t sOffA = (uint32_t)(lr * PITCH_B + ck * 16);
    const uint32_t sOffB = (uint32_t)(TILE_BYTES + lr * PITCH_B + ck * 16);

    float acc[2][8][4];
    #pragma unroll
    for (int mt = 0; mt < 2; mt++)
        #pragma unroll
        for (int nt = 0; nt < 8; nt++)
            #pragma unroll
            for (int e = 0; e < 4; e++) acc[mt][nt][e] = 0.f;

    const uint32_t aBase = sbase + (uint32_t)((warpM * 32 + (lane & 15)) * PITCH_B +
                                              (lane >> 4) * 16);
    const uint32_t bBase = sbase + TILE_BYTES +
                           (uint32_t)((warpN * 64 + (lane & 15)) * PITCH_B +
                                      (lane >> 4) * 16);

    // --- mask chunk issue: chunk k covers region k>>2, rows (k&3)*32..+32 ---
    auto issue_chunk = [&](int k) {
        if (!offdiag && k >= 8) return;       // diag: no transposed regions
        const int region = k >> 2;
        const int rb = (region & 3, (k & 3) * 32);
        const int* mb = (region & 1) ? neg : pos;
        const bool colside = (region >= 2);
        const uint32_t dstBase = sbase + OFF_MSTAGE + (uint32_t)((k & 1) * MSTAGE_BYTES);
        #pragma unroll
        for (int c = 0; c < 4; c++) {
            const int Q = c * 256 + tid;       // 0..1023 quads
            const int gq = Q >> 3;             // word 0..127
            const int qw = Q & 7;              // quad within word
            const int rl = rb + (gq >> 2);     // local row 0..127
            const int w = gq & 3;
            const size_t src = colside
                ? (size_t)(colBase + rl) * NROWS + rowBase + w * 32 + qw * 4
                : (size_t)(rowBase + rl) * NROWS + colBase + w * 32 + qw * 4;
            cp16(dstBase + (uint32_t)(gq * 128 + qw * 16), mb + src);
        }
    };

    // prologue: stages 0,1 + chunks 0,1 (groups G0, G1)
    #pragma unroll
    for (int kp = 0; kp < 2; kp++) {
        const uint32_t st = sbase + kp * STAGE_BYTES;
        const size_t go = (size_t)kp * BK;
        cp16(st + sOffA, gA + go);
        cp16(st + sOffA + 64 * PITCH_B, gA + go + (size_t)64 * DDIM);
        cp16(st + sOffB, gB + go);
        cp16(st + sOffB + 64 * PITCH_B, gB + go + (size_t)64 * DDIM);
        issue_chunk(kp);
        cp_commit();
    }

    for (int kt = 0; kt < NKT; kt++) {
        cp_wait1();          // stage kt + chunk kt landed
        __syncthreads();     // + prev stage reads done before reuse

        // compress chunk kt: 4096 ints -> 128 bit words (16 per warp)
        if (offdiag || kt < 8) {
            const int* stg = smStage + (kt & 1) * (MSTAGE_BYTES / 4);
            #pragma unroll
            for (int t = 0; t < 16; t++) {
                const int gq = wid * 16 + t;
                const int v = stg[gq * 32 + lane];
                const uint32_t wd = __ballot_sync(0xffffffffu, v != 0);
                if (lane == 0) smBits[kt * 128 + gq] = wd;
            }
        }
        __syncthreads();     // compress reads done before staging slot rewrite

        if (kt + 2 < NKT) {
            const uint32_t st = sbase + ((kt + 2) % NST) * STAGE_BYTES;
            const size_t go = (size_t)(kt + 2) * BK;
            cp16(st + sOffA, gA + go);
            cp16(st + sOffA + 64 * PITCH_B, gA + go + (size_t)64 * DDIM);
            cp16(st + sOffB, gB + go);
            cp16(st + sOffB + 64 * PITCH_B, gB + go + (size_t)64 * DDIM);
            issue_chunk(kt + 2);
        }
        cp_commit();

        const uint32_t stOff = (kt % NST) * STAGE_BYTES;
        #pragma unroll
        for (int ks = 0; ks < 2; ks++) {
            uint32_t areg[2][4];
            #pragma unroll
            for (int mt = 0; mt < 2; mt++)
                ldm_x4(aBase + stOff + mt * 16 * PITCH_B + ks * 32,
                       areg[mt][0], areg[mt][1], areg[mt][2], areg[mt][3]);
            uint32_t breg[4][4];
            #pragma unroll
            for (int p = 0; p < 4; p++)
                ldm_x4(bBase + stOff + p * 16 * PITCH_B + ks * 32,
                       breg[p][0], breg[p][1], breg[p][2], breg[p][3]);
            #pragma unroll
            for (int mt = 0; mt < 2; mt++)
                #pragma unroll
                for (int nt = 0; nt < 8; nt++) {
                    const int p = nt >> 1, hi = nt & 1;
                    mma16816(acc[mt][nt], areg[mt],
                             breg[p][hi ? 1 : 0], breg[p][hi ? 3 : 2]);
                }
        }
    }
    __syncthreads();   // last compress visible

    // ---- epilogue 1: row-oriented. x = exp2f(acc*C) overwrites acc; e = x*Ei.
    #pragma unroll
    for (int mt = 0; mt < 2; mt++) {
        const int r0l = warpM * 32 + mt * 16 + (lane >> 2);
        const int r1l = r0l + 8;
        const int r0 = rowBase + r0l;
        const int r1 = rowBase + r1l;
        const float EiA = g_einv[r0];
        const float EiB = g_einv[r1];
        // bit words: posRow [0,512), negRow [512,1024); 4 words per row
        const uint32_t pA0 = smBits[r0l * 4 + warpN * 2];
        const uint32_t pA1 = smBits[r0l * 4 + warpN * 2 + 1];
        const uint32_t nA0 = smBits[512 + r0l * 4 + warpN * 2];
        const uint32_t nA1 = smBits[512 + r0l * 4 + warpN * 2 + 1];
        const uint32_t pB0 = smBits[r1l * 4 + warpN * 2];
        const uint32_t pB1 = smBits[r1l * 4 + warpN * 2 + 1];
        const uint32_t nB0 = smBits[512 + r1l * 4 + warpN * 2];
        const uint32_t nB1 = smBits[512 + r1l * 4 + warpN * 2 + 1];
        float sp0 = 0.f, sn0 = 0.f, cd0 = 0.f;
        float sp1 = 0.f, sn1 = 0.f, cd1 = 0.f;
        #pragma unroll
        for (int nt = 0; nt < 8; nt++) {
            const int j = colBase + warpN * 64 + nt * 8 + (lane & 3) * 2;
            const int b = (nt & 3) * 8 + (lane & 3) * 2;
            const uint32_t pw0 = (nt < 4) ? pA0 : pA1;
            const uint32_t nw0 = (nt < 4) ? nA0 : nA1;
            const uint32_t pw1 = (nt < 4) ? pB0 : pB1;
            const uint32_t nw1 = (nt < 4) ? nB0 : nB1;
            const float x00 = exp2f(acc[mt][nt][0] * EXP_C2);
            const float x01 = exp2f(acc[mt][nt][1] * EXP_C2);
            const float x10 = exp2f(acc[mt][nt][2] * EXP_C2);
            const float x11 = exp2f(acc[mt][nt][3] * EXP_C2);
            acc[mt][nt][0] = x00; acc[mt][nt][1] = x01;
            acc[mt][nt][2] = x10; acc[mt][nt][3] = x11;
            const float e00 = x00 * EiA, e01 = x01 * EiA;
            const float e10 = x10 * EiB, e11 = x11 * EiB;
            const bool v00 = (j != r0), v01 = (j + 1 != r0);
            const bool v10 = (j != r1), v11 = (j + 1 != r1);
            if (((pw0 >> b) & 1) && v00) { sp0 += e00; cd0 += 1.f; }
            if (((pw0 >> (b + 1)) & 1) && v01) { sp0 += e01; cd0 += 1.f; }
            if (((nw0 >> b) & 1) && v00) sn0 += e00;
            if (((nw0 >> (b + 1)) & 1) && v01) sn0 += e01;
            if (((pw1 >> b) & 1) && v10) { sp1 += e10; cd1 += 1.f; }
            if (((pw1 >> (b + 1)) & 1) && v11) { sp1 += e11; cd1 += 1.f; }
            if (((nw1 >> b) & 1) && v10) sn1 += e10;
            if (((nw1 >> (b + 1)) & 1) && v11) sn1 += e11;
        }
        #pragma unroll
        for (int o = 1; o <= 2; o <<= 1) {
            sp0 += __shfl_xor_sync(0xffffffffu, sp0, o);
            sn0 += __shfl_xor_sync(0xffffffffu, sn0, o);
            cd0 += __shfl_xor_sync(0xffffffffu, cd0, o);
            sp1 += __shfl_xor_sync(0xffffffffu, sp1, o);
            sn1 += __shfl_xor_sync(0xffffffffu, sn1, o);
            cd1 += __shfl_xor_sync(0xffffffffu, cd1, o);
        }
        if ((lane & 3) == 0) {
            atomicAdd(&g_spos[r0], sp0);
            atomicAdd(&g_sneg[r0], sn0);
            atomicAdd(&g_card[r0], cd0);
            atomicAdd(&g_spos[r1], sp1);
            atomicAdd(&g_sneg[r1], sn1);
            atomicAdd(&g_card[r1], cd1);
        }
    }

    // ---- epilogue 2 (off-diag): column-oriented, e' = x * Ej (x reused).
    if (offdiag) {
        #pragma unroll
        for (int nt = 0; nt < 8; nt++) {
            const int j0l = warpN * 64 + nt * 8 + (lane & 3) * 2;
            const int j0 = colBase + j0l;
            const int j1 = j0 + 1;
            const float Ej0 = g_einv[j0];
            const float Ej1 = g_einv[j1];
            // posCol [1024,1536), negCol [1536,2048); 4 words per col row
            const uint32_t cp0 = smBits[1024 + j0l * 4 + warpM];
            const uint32_t cn0 = smBits[1536 + j0l * 4 + warpM];
            const uint32_t cp1 = smBits[1024 + (j0l + 1) * 4 + warpM];
            const uint32_t cn1 = smBits[1536 + (j0l + 1) * 4 + warpM];
            float spc0 = 0.f, snc0 = 0.f, cdc0 = 0.f;
            float spc1 = 0.f, snc1 = 0.f, cdc1 = 0.f;
            #pragma unroll
            for (int mt = 0; mt < 2; mt++) {
                const int b0 = mt * 16 + (lane >> 2);
                const int b1 = b0 + 8;
                const float e00 = acc[mt][nt][0] * Ej0;  // (r0,j0)
                const float e01 = acc[mt][nt][1] * Ej1;  // (r0,j1)
                const float e10 = acc[mt][nt][2] * Ej0;  // (r1,j0)
                const float e11 = acc[mt][nt][3] * Ej1;  // (r1,j1)
                if ((cp0 >> b0) & 1) { spc0 += e00; cdc0 += 1.f; }
                if ((cp0 >> b1) & 1) { spc0 += e10; cdc0 += 1.f; }
                if ((cn0 >> b0) & 1) snc0 += e00;
                if ((cn0 >> b1) & 1) snc0 += e10;
                if ((cp1 >> b0) & 1) { spc1 += e01; cdc1 += 1.f; }
                if ((cp1 >> b1) & 1) { spc1 += e11; cdc1 += 1.f; }
                if ((cn1 >> b0) & 1) snc1 += e01;
                if ((cn1 >> b1) & 1) snc1 += e11;
            }
            #pragma unroll
            for (int o = 4; o <= 16; o <<= 1) {
                spc0 += __shfl_xor_sync(0xffffffffu, spc0, o);
                snc0 += __shfl_xor_sync(0xffffffffu, snc0, o);
                cdc0 += __shfl_xor_sync(0xffffffffu, cdc0, o);
                spc1 += __shfl_xor_sync(0xffffffffu, spc1, o);
                snc1 += __shfl_xor_sync(0xffffffffu, snc1, o);
                cdc1 += __shfl_xor_sync(0xffffffffu, cdc1, o);
            }
            if (lane < 4) {
                atomicAdd(&g_spos[j0], spc0);
                atomicAdd(&g_sneg[j0], snc0);
                atomicAdd(&g_card[j0], cdc0);
                atomicAdd(&g_spos[j1], spc1);
                atomicAdd(&g_sneg[j1], snc1);
                atomicAdd(&g_card[j1], cdc1);
            }
        }
    }
}

// ---------------------------------------------------------------------------
// Kernel 3: finalize (parallel, atomicAdd of scaled partials)
// ---------------------------------------------------------------------------
__global__ __launch_bounds__(256) void k_finalize(float* __restrict__ out) {
    __shared__ float s[256];
    const int i = blockIdx.x * 256 + threadIdx.x;
    float c = g_card[i];
    float l = 0.f;
    if (c > 0.f) l = logf(g_sneg[i]) - g_spos[i] / c;
    s[threadIdx.x] = l;
    __syncthreads();
    #pragma unroll
    for (int st = 128; st; st >>= 1) {
        if (threadIdx.x < st) s[threadIdx.x] += s[threadIdx.x + st];
        __syncthreads();
    }
    if (threadIdx.x == 0) atomicAdd(out, s[0] * (1.0f / (float)NROWS));
}

// ---------------------------------------------------------------------------
extern "C" void kernel_launch(void* const* d_in, const int* in_sizes, int n_in,
                              void* d_out, int out_size) {
    const float* feat = (const float*)d_in[0];
    const int* pos = (const int*)d_in[1];
    const int* neg = (const int*)d_in[2];
    float* out = (float*)d_out;

    cudaFuncSetAttribute(k_main, cudaFuncAttributeMaxDynamicSharedMemorySize,
                         SMEM_MAIN);

    k_normalize<<<NROWS, 128>>>(feat, out);
    k_main<<<NPAIR, THREADS, SMEM_MAIN>>>(pos, neg);
    k_finalize<<<NROWS / 256, 256>>>(out);
}

// round 14
// speedup vs baseline: 1.1087x; 1.1087x over previous
#include <cuda_runtime.h>
#include <cuda_fp16.h>
#include <math.h>
#include <stdint.h>

// ===========================================================================
// MySupConLoss fused, round 12: R9 structure (best) + post-loop coalesced
// ballot-compress of the TRANSPOSED mask region into SMEM bits.
//   - k-loop identical to R9 (3-stage cp.async, 1 sync/kt, L2 mask prefetch)
//   - epilogue 2 previously did scalar 4B transposed reads (4x sector
//     amplification, ~512 MB L2 sectors). Now: after the k-loop, each warp
//     reads mask[colBase+j][rowBase+w*32+lane] coalesced (L2-hot from the
//     prefetch), ballots to bit words in a 4 KB SMEM array; ep2 reads bits.
// ===========================================================================

#define NROWS 8192
#define DDIM  512
#define INV_T 14.285714285714286f
#define EXP_C2 20.60992915555662f   // INV_T * log2(e)

#define BM 128
#define BN 128
#define BK 32
#define NKT (DDIM / BK)        // 16
#define PITCH_B 80             // bytes per smem row (32 halves + 8 pad)
#define TILE_BYTES (128 * PITCH_B)      // 10240
#define STAGE_BYTES (2 * TILE_BYTES)    // 20480 (A + B)
#define NST 3
#define GEMM_SMEM (NST * STAGE_BYTES)   // 61440
#define OFF_BITS  GEMM_SMEM
#define SMEM_MAIN (OFF_BITS + 1024 * 4) // 65536 -> still 2 CTAs/SM
#define THREADS 256
#define NBLK (NROWS / BM)
#define NPAIR (NBLK * (NBLK + 1) / 2)   // 2080

// ---------------------------------------------------------------------------
__device__ __half g_fn16[(size_t)NROWS * DDIM];
__device__ float  g_einv[NROWS];   // exp(-m_i)
__device__ float  g_spos[NROWS];
__device__ float  g_sneg[NROWS];
__device__ float  g_card[NROWS];

// ---------------------------------------------------------------------------
__device__ __forceinline__ uint32_t smem_u32(const void* p) {
    uint32_t a;
    asm("{ .reg .u64 t; cvta.to.shared.u64 t, %1; cvt.u32.u64 %0, t; }"
        : "=r"(a) : "l"(p));
    return a;
}
__device__ __forceinline__ void cp16(uint32_t s, const void* g) {
    asm volatile("cp.async.cg.shared.global [%0], [%1], 16;"
                 :: "r"(s), "l"(g) : "memory");
}
__device__ __forceinline__ void cp_commit() {
    asm volatile("cp.async.commit_group;" ::: "memory");
}
__device__ __forceinline__ void cp_wait1() {
    asm volatile("cp.async.wait_group 1;" ::: "memory");
}
__device__ __forceinline__ void l2_prefetch(const void* g) {
    asm volatile("prefetch.global.L2 [%0];" :: "l"(g));
}
__device__ __forceinline__ void ldm_x4(uint32_t a, uint32_t& r0, uint32_t& r1,
                                       uint32_t& r2, uint32_t& r3) {
    asm volatile("ldmatrix.sync.aligned.m8n8.x4.shared.b16 {%0,%1,%2,%3}, [%4];"
                 : "=r"(r0), "=r"(r1), "=r"(r2), "=r"(r3) : "r"(a));
}
__device__ __forceinline__ void mma16816(float* c, const uint32_t* a,
                                         uint32_t b0, uint32_t b1) {
    asm volatile(
        "mma.sync.aligned.m16n8k16.row.col.f32.f16.f16.f32 "
        "{%0,%1,%2,%3}, {%4,%5,%6,%7}, {%8,%9}, {%0,%1,%2,%3};"
        : "+f"(c[0]), "+f"(c[1]), "+f"(c[2]), "+f"(c[3])
        : "r"(a[0]), "r"(a[1]), "r"(a[2]), "r"(a[3]), "r"(b0), "r"(b1));
}

// ---------------------------------------------------------------------------
// Kernel 1: normalize -> fp16, einv = exp(-m_i), zero accumulators + out
// ---------------------------------------------------------------------------
__global__ __launch_bounds__(128) void k_normalize(const float* __restrict__ f,
                                                   float* __restrict__ out) {
    int row = blockIdx.x;
    const float4* fr = reinterpret_cast<const float4*>(f + (size_t)row * DDIM);
    float4 v = fr[threadIdx.x];
    float ss = v.x * v.x + v.y * v.y + v.z * v.z + v.w * v.w;
    #pragma unroll
    for (int o = 16; o; o >>= 1) ss += __shfl_xor_sync(0xffffffffu, ss, o);
    __shared__ float s[4];
    if ((threadIdx.x & 31) == 0) s[threadIdx.x >> 5] = ss;
    __syncthreads();
    float tot = s[0] + s[1] + s[2] + s[3];
    float inv = 1.0f / fmaxf(sqrtf(tot), 1e-8f);
    __half2 h0 = __floats2half2_rn(v.x * inv, v.y * inv);
    __half2 h1 = __floats2half2_rn(v.z * inv, v.w * inv);
    __half2* o2 = reinterpret_cast<__half2*>(g_fn16 + (size_t)row * DDIM);
    o2[threadIdx.x * 2 + 0] = h0;
    o2[threadIdx.x * 2 + 1] = h1;
    if (threadIdx.x == 0) {
        g_einv[row] = expf(-(tot * inv * inv * INV_T));
        g_spos[row] = 0.f; g_sneg[row] = 0.f; g_card[row] = 0.f;
        if (row == 0) out[0] = 0.f;
    }
}

// ---------------------------------------------------------------------------
// Kernel 2: fused symmetric GEMM + dual epilogue.
// ---------------------------------------------------------------------------
__global__ __launch_bounds__(THREADS, 2) void k_main(const int* __restrict__ pos,
                                                     const int* __restrict__ neg) {
    extern __shared__ __align__(16) char smem_raw[];
    const uint32_t sbase = smem_u32(smem_raw);
    uint32_t* const smBits = reinterpret_cast<uint32_t*>(smem_raw + OFF_BITS);

    // linear block id -> upper-triangular (bi <= bj)
    int idx = blockIdx.x, bi = 0, len = NBLK;
    while (idx >= len) { idx -= len; bi++; len--; }
    const int bj = bi + idx;
    const bool offdiag = (bi != bj);

    const int tid = threadIdx.x;
    const int wid = tid >> 5;
    const int lane = tid & 31;
    const int warpM = wid & 3;
    const int warpN = wid >> 2;
    const int rowBase = bi * BM;
    const int colBase = bj * BN;

    const int lr = tid >> 2;
    const int ck = tid & 3;
    const __half* gA = g_fn16 + (size_t)(rowBase + lr) * DDIM + ck * 8;
    const __half* gB = g_fn16 + (size_t)(colBase + lr) * DDIM + ck * 8;
    const uint32_t sOffA = (uint32_t)(lr * PITCH_B + ck * 16);
    const uint32_t sOffB = (uint32_t)(TILE_BYTES + lr * PITCH_B + ck * 16);

    float acc[2][8][4];
    #pragma unroll
    for (int mt = 0; mt < 2; mt++)
        #pragma unroll
        for (int nt = 0; nt < 8; nt++)
            #pragma unroll
            for (int e = 0; e < 4; e++) acc[mt][nt][e] = 0.f;

    const uint32_t aBase = sbase + (uint32_t)((warpM * 32 + (lane & 15)) * PITCH_B +
                                              (lane >> 4) * 16);
    const uint32_t bBase = sbase + TILE_BYTES +
                           (uint32_t)((warpN * 64 + (lane & 15)) * PITCH_B +
                                      (lane >> 4) * 16);

    // prologue: stages 0,1 <- kt 0,1
    #pragma unroll
    for (int kp = 0; kp < 2; kp++) {
        const uint32_t st = sbase + kp * STAGE_BYTES;
        const size_t go = (size_t)kp * BK;
        cp16(st + sOffA, gA + go);
        cp16(st + sOffA + 64 * PITCH_B, gA + go + (size_t)64 * DDIM);
        cp16(st + sOffB, gB + go);
        cp16(st + sOffB + 64 * PITCH_B, gB + go + (size_t)64 * DDIM);
        cp_commit();
    }

    for (int kt = 0; kt < NKT; kt++) {
        cp_wait1();
        __syncthreads();

        // L2 prefetch of this block's mask regions, spread over the k-loop.
        if (tid < 128) {
            const int reg = kt >> 2;
            const int li = ((kt & 3) << 7) + tid;
            const int rr = li >> 2;
            const int off = (li & 3) << 5;
            const int* base = (reg & 1) ? neg : pos;
            const size_t adr = (reg < 2)
                ? (size_t)(rowBase + rr) * NROWS + colBase + off
                : (size_t)(colBase + rr) * NROWS + rowBase + off;
            l2_prefetch(base + adr);
        }

        if (kt + 2 < NKT) {
            const uint32_t st = sbase + ((kt + 2) % NST) * STAGE_BYTES;
            const size_t go = (size_t)(kt + 2) * BK;
            cp16(st + sOffA, gA + go);
            cp16(st + sOffA + 64 * PITCH_B, gA + go + (size_t)64 * DDIM);
            cp16(st + sOffB, gB + go);
            cp16(st + sOffB + 64 * PITCH_B, gB + go + (size_t)64 * DDIM);
        }
        cp_commit();

        const uint32_t stOff = (kt % NST) * STAGE_BYTES;
        #pragma unroll
        for (int ks = 0; ks < 2; ks++) {
            uint32_t areg[2][4];
            #pragma unroll
            for (int mt = 0; mt < 2; mt++)
                ldm_x4(aBase + stOff + mt * 16 * PITCH_B + ks * 32,
                       areg[mt][0], areg[mt][1], areg[mt][2], areg[mt][3]);
            uint32_t breg[4][4];
            #pragma unroll
            for (int p = 0; p < 4; p++)
                ldm_x4(bBase + stOff + p * 16 * PITCH_B + ks * 32,
                       breg[p][0], breg[p][1], breg[p][2], breg[p][3]);
            #pragma unroll
            for (int mt = 0; mt < 2; mt++)
                #pragma unroll
                for (int nt = 0; nt < 8; nt++) {
                    const int p = nt >> 1, hi = nt & 1;
                    mma16816(acc[mt][nt], areg[mt],
                             breg[p][hi ? 1 : 0], breg[p][hi ? 3 : 2]);
                }
        }
    }

    // ---- one-shot coalesced compress of the transposed mask region ----
    // smBits: [0,512) posCol, [512,1024) negCol; word = j*4 + w, bit = lane
    // (r = rowBase + w*32 + lane). Loads are 128B coalesced, L2-hot.
    if (offdiag) {
        for (int t = 0; t < 16; t++) {
            const int j = wid * 16 + t;
            const size_t ro = (size_t)(colBase + j) * NROWS + rowBase;
            #pragma unroll
            for (int w = 0; w < 4; w++) {
                const int pv = pos[ro + w * 32 + lane];
                const int nv = neg[ro + w * 32 + lane];
                const uint32_t pb = __ballot_sync(0xffffffffu, pv != 0);
                const uint32_t nb = __ballot_sync(0xffffffffu, nv != 0);
                if (lane == 0) {
                    smBits[j * 4 + w] = pb;
                    smBits[512 + j * 4 + w] = nb;
                }
            }
        }
    }
    __syncthreads();

    // ---- epilogue 1: row-oriented. x = exp2f(acc*C) overwrites acc; e = x*Ei.
    #pragma unroll
    for (int mt = 0; mt < 2; mt++) {
        const int r0 = rowBase + warpM * 32 + mt * 16 + (lane >> 2);
        const int r1 = r0 + 8;
        const float EiA = g_einv[r0];
        const float EiB = g_einv[r1];
        const size_t o0 = (size_t)r0 * NROWS;
        const size_t o1 = (size_t)r1 * NROWS;
        float sp0 = 0.f, sn0 = 0.f, cd0 = 0.f;
        float sp1 = 0.f, sn1 = 0.f, cd1 = 0.f;
        #pragma unroll
        for (int nt = 0; nt < 8; nt++) {
            const int j = colBase + warpN * 64 + nt * 8 + (lane & 3) * 2;
            const float x00 = exp2f(acc[mt][nt][0] * EXP_C2);
            const float x01 = exp2f(acc[mt][nt][1] * EXP_C2);
            const float x10 = exp2f(acc[mt][nt][2] * EXP_C2);
            const float x11 = exp2f(acc[mt][nt][3] * EXP_C2);
            acc[mt][nt][0] = x00; acc[mt][nt][1] = x01;
            acc[mt][nt][2] = x10; acc[mt][nt][3] = x11;
            const float e00 = x00 * EiA, e01 = x01 * EiA;
            const float e10 = x10 * EiB, e11 = x11 * EiB;
            const int2 p0 = *reinterpret_cast<const int2*>(pos + o0 + j);
            const int2 n0 = *reinterpret_cast<const int2*>(neg + o0 + j);
            const int2 p1 = *reinterpret_cast<const int2*>(pos + o1 + j);
            const int2 n1 = *reinterpret_cast<const int2*>(neg + o1 + j);
            const bool v00 = (j != r0), v01 = (j + 1 != r0);
            const bool v10 = (j != r1), v11 = (j + 1 != r1);
            if (p0.x && v00) { sp0 += e00; cd0 += 1.f; }
            if (p0.y && v01) { sp0 += e01; cd0 += 1.f; }
            if (n0.x && v00) sn0 += e00;
            if (n0.y && v01) sn0 += e01;
            if (p1.x && v10) { sp1 += e10; cd1 += 1.f; }
            if (p1.y && v11) { sp1 += e11; cd1 += 1.f; }
            if (n1.x && v10) sn1 += e10;
            if (n1.y && v11) sn1 += e11;
        }
        #pragma unroll
        for (int o = 1; o <= 2; o <<= 1) {
            sp0 += __shfl_xor_sync(0xffffffffu, sp0, o);
            sn0 += __shfl_xor_sync(0xffffffffu, sn0, o);
            cd0 += __shfl_xor_sync(0xffffffffu, cd0, o);
            sp1 += __shfl_xor_sync(0xffffffffu, sp1, o);
            sn1 += __shfl_xor_sync(0xffffffffu, sn1, o);
            cd1 += __shfl_xor_sync(0xffffffffu, cd1, o);
        }
        if ((lane & 3) == 0) {
            atomicAdd(&g_spos[r0], sp0);
            atomicAdd(&g_sneg[r0], sn0);
            atomicAdd(&g_card[r0], cd0);
            atomicAdd(&g_spos[r1], sp1);
            atomicAdd(&g_sneg[r1], sn1);
            atomicAdd(&g_card[r1], cd1);
        }
    }

    // ---- epilogue 2 (off-diag): column-oriented, bits from SMEM, e' = x*Ej.
    if (offdiag) {
        #pragma unroll
        for (int nt = 0; nt < 8; nt++) {
            const int j0l = warpN * 64 + nt * 8 + (lane & 3) * 2;
            const int j0 = colBase + j0l;
            const int j1 = j0 + 1;
            const float Ej0 = g_einv[j0];
            const float Ej1 = g_einv[j1];
            const uint32_t cp0 = smBits[j0l * 4 + warpM];
            const uint32_t cn0 = smBits[512 + j0l * 4 + warpM];
            const uint32_t cp1 = smBits[(j0l + 1) * 4 + warpM];
            const uint32_t cn1 = smBits[512 + (j0l + 1) * 4 + warpM];
            float spc0 = 0.f, snc0 = 0.f, cdc0 = 0.f;
            float spc1 = 0.f, snc1 = 0.f, cdc1 = 0.f;
            #pragma unroll
            for (int mt = 0; mt < 2; mt++) {
                const int b0 = mt * 16 + (lane >> 2);
                const int b1 = b0 + 8;
                const float e00 = acc[mt][nt][0] * Ej0;  // (r0,j0)
                const float e01 = acc[mt][nt][1] * Ej1;  // (r0,j1)
                const float e10 = acc[mt][nt][2] * Ej0;  // (r1,j0)
                const float e11 = acc[mt][nt][3] * Ej1;  // (r1,j1)
                if ((cp0 >> b0) & 1) { spc0 += e00; cdc0 += 1.f; }
                if ((cp0 >> b1) & 1) { spc0 += e10; cdc0 += 1.f; }
                if ((cn0 >> b0) & 1) snc0 += e00;
                if ((cn0 >> b1) & 1) snc0 += e10;
                if ((cp1 >> b0) & 1) { spc1 += e01; cdc1 += 1.f; }
                if ((cp1 >> b1) & 1) { spc1 += e11; cdc1 += 1.f; }
                if ((cn1 >> b0) & 1) snc1 += e01;
                if ((cn1 >> b1) & 1) snc1 += e11;
            }
            #pragma unroll
            for (int o = 4; o <= 16; o <<= 1) {
                spc0 += __shfl_xor_sync(0xffffffffu, spc0, o);
                snc0 += __shfl_xor_sync(0xffffffffu, snc0, o);
                cdc0 += __shfl_xor_sync(0xffffffffu, cdc0, o);
                spc1 += __shfl_xor_sync(0xffffffffu, spc1, o);
                snc1 += __shfl_xor_sync(0xffffffffu, snc1, o);
                cdc1 += __shfl_xor_sync(0xffffffffu, cdc1, o);
            }
            if (lane < 4) {
                atomicAdd(&g_spos[j0], spc0);
                atomicAdd(&g_sneg[j0], snc0);
                atomicAdd(&g_card[j0], cdc0);
                atomicAdd(&g_spos[j1], spc1);
                atomicAdd(&g_sneg[j1], snc1);
                atomicAdd(&g_card[j1], cdc1);
            }
        }
    }
}

// ---------------------------------------------------------------------------
// Kernel 3: finalize (parallel, atomicAdd of scaled partials)
// ---------------------------------------------------------------------------
__global__ __launch_bounds__(256) void k_finalize(float* __restrict__ out) {
    __shared__ float s[256];
    const int i = blockIdx.x * 256 + threadIdx.x;
    float c = g_card[i];
    float l = 0.f;
    if (c > 0.f) l = logf(g_sneg[i]) - g_spos[i] / c;
    s[threadIdx.x] = l;
    __syncthreads();
    #pragma unroll
    for (int st = 128; st; st >>= 1) {
        if (threadIdx.x < st) s[threadIdx.x] += s[threadIdx.x + st];
        __syncthreads();
    }
    if (threadIdx.x == 0) atomicAdd(out, s[0] * (1.0f / (float)NROWS));
}

// ---------------------------------------------------------------------------
extern "C" void kernel_launch(void* const* d_in, const int* in_sizes, int n_in,
                              void* d_out, int out_size) {
    const float* feat = (const float*)d_in[0];
    const int* pos = (const int*)d_in[1];
    const int* neg = (const int*)d_in[2];
    float* out = (float*)d_out;

    cudaFuncSetAttribute(k_main, cudaFuncAttributeMaxDynamicSharedMemorySize,
                         SMEM_MAIN);

    k_normalize<<<NROWS, 128>>>(feat, out);
    k_main<<<NPAIR, THREADS, SMEM_MAIN>>>(pos, neg);
    k_finalize<<<NROWS / 256, 256>>>(out);
}